// round 16
// baseline (speedup 1.0000x reference)
#include <cuda_runtime.h>
#include <cuda_fp16.h>
#include <math.h>

// ---------------- scratch (device globals; no allocations allowed) ----------------
__device__ __half g_q1h[128u * 65536u];         // 16 MB : conv1 q out (NCHW, fp16)
__device__ __half g_k1h[128u * 65536u];         // 16 MB : conv1 k out (NCHW, fp16)
__device__ float  g_v1[128u * 65536u];          // 32 MB : conv1 v out (NCHW, fp32)
__device__ __half g_qw16[256u * 128u * 256u];   // 16 MB : q  [win][c][m] fp16
__device__ __half g_kw16[256u * 128u * 256u];   // 16 MB : k  [win][c][m] fp16
__device__ float  g_vw[256u * 128u * 256u];     // 32 MB : v  [win][c][m] fp32
__device__ float  g_outw[128u * 65536u];        // 32 MB : out_win [win][c][m]

// =====================================================================================
// helpers
// =====================================================================================
__device__ __forceinline__ unsigned f2tf32(float f) {
    unsigned u;
    asm("cvt.rna.tf32.f32 %0, %1;" : "=r"(u) : "f"(f));
    return u;
}
__device__ __forceinline__ float ex2f(float x) {
    float r;
    asm("ex2.approx.f32 %0, %1;" : "=f"(r) : "f"(x));
    return r;
}
__device__ __forceinline__ void mma_tf32(float c[4], const unsigned a[4], const unsigned b[2]) {
    asm volatile(
        "mma.sync.aligned.m16n8k8.row.col.f32.tf32.tf32.f32 "
        "{%0,%1,%2,%3},{%4,%5,%6,%7},{%8,%9},{%0,%1,%2,%3};"
        : "+f"(c[0]), "+f"(c[1]), "+f"(c[2]), "+f"(c[3])
        : "r"(a[0]), "r"(a[1]), "r"(a[2]), "r"(a[3]), "r"(b[0]), "r"(b[1]));
}
__device__ __forceinline__ void mma_f16(float c[4], const unsigned a[4], const unsigned b[2]) {
    asm volatile(
        "mma.sync.aligned.m16n8k16.row.col.f32.f16.f16.f32 "
        "{%0,%1,%2,%3},{%4,%5,%6,%7},{%8,%9},{%0,%1,%2,%3};"
        : "+f"(c[0]), "+f"(c[1]), "+f"(c[2]), "+f"(c[3])
        : "r"(a[0]), "r"(a[1]), "r"(a[2]), "r"(a[3]), "r"(b[0]), "r"(b[1]));
}
__device__ __forceinline__ unsigned h2u(__half2 h) { return *reinterpret_cast<unsigned*>(&h); }

// =====================================================================================
// K1: LN + 1x1 convs as tf32 tensor GEMM with x hi/lo compensation. (unchanged)
// =====================================================================================
__global__ void __launch_bounds__(256, 2) k1_ln_conv1(
    const float* __restrict__ lms, const float* __restrict__ pan,
    const float* __restrict__ gms, const float* __restrict__ gpan,
    const float* __restrict__ qw1, const float* __restrict__ qb1,
    const float* __restrict__ kvw1, const float* __restrict__ kvb1)
{
    extern __shared__ float sw[];
    unsigned* Xh = (unsigned*)sw;            // 64 x 136
    unsigned* Xl = (unsigned*)(sw + 8704);   // 64 x 136

    int t = threadIdx.x;
    int lane = t & 31, w = t >> 5;
    int g = lane >> 2, tig = lane & 3;
    int p0 = blockIdx.x * 128;

    unsigned a[3][4][4];
    float bias0[3], bias1[3];
#pragma unroll
    for (int j = 0; j < 3; j++) {
        int R = j * 128 + w * 16;
        const float* Wsrc = (j == 0) ? qw1 : kvw1;
        int r0 = (j == 0) ? R : (R - 128);
#pragma unroll
        for (int ks = 0; ks < 4; ks++) {
            int k0 = ks * 8;
            a[j][ks][0] = f2tf32(Wsrc[(r0 + g) * 32 + k0 + tig]);
            a[j][ks][1] = f2tf32(Wsrc[(r0 + 8 + g) * 32 + k0 + tig]);
            a[j][ks][2] = f2tf32(Wsrc[(r0 + g) * 32 + k0 + tig + 4]);
            a[j][ks][3] = f2tf32(Wsrc[(r0 + 8 + g) * 32 + k0 + tig + 4]);
        }
        const float* Bsrc = (j == 0) ? qb1 : kvb1;
        bias0[j] = Bsrc[r0 + g];
        bias1[j] = Bsrc[r0 + 8 + g];
    }

    {
        int which = t >> 7;
        int px = t & 127;
        const float* src = which ? lms : pan;
        const float* gg  = which ? gms : gpan;
        float x[32];
        float s = 0.f, s2 = 0.f;
#pragma unroll
        for (int i = 0; i < 32; i++) {
            float v = src[i * 65536 + p0 + px];
            x[i] = v; s += v; s2 += v * v;
        }
        float m = s * (1.f / 32.f);
        float var = s2 * (1.f / 32.f) - m * m;
        float r = rsqrtf(var + 1e-5f);
#pragma unroll
        for (int i = 0; i < 32; i++) {
            float xn = (x[i] - m) * r * gg[i];
            unsigned xh = f2tf32(xn);
            unsigned xl = f2tf32(xn - __uint_as_float(xh));
            int row = which * 32 + i;
            Xh[row * 136 + px] = xh;
            Xl[row * 136 + px] = xl;
        }
    }
    __syncthreads();

    for (int nt = 0; nt < 16; nt++) {
        int n0 = nt * 8;
#pragma unroll
        for (int j = 0; j < 3; j++) {
            int xrow = (j > 0) ? 32 : 0;
            float c[4] = {bias0[j], bias0[j], bias1[j], bias1[j]};
#pragma unroll
            for (int ks = 0; ks < 4; ks++) {
                int k0 = ks * 8;
                unsigned bh[2] = { Xh[(xrow + k0 + tig) * 136 + n0 + g],
                                   Xh[(xrow + k0 + tig + 4) * 136 + n0 + g] };
                mma_tf32(c, a[j][ks], bh);
                unsigned bl[2] = { Xl[(xrow + k0 + tig) * 136 + n0 + g],
                                   Xl[(xrow + k0 + tig + 4) * 136 + n0 + g] };
                mma_tf32(c, a[j][ks], bl);
            }
            int r = w * 16 + g;
            size_t px = (size_t)(p0 + n0 + tig * 2);
            if (j == 0) {
                *(__half2*)&g_q1h[(size_t)r * 65536 + px]       = __floats2half2_rn(c[0], c[1]);
                *(__half2*)&g_q1h[(size_t)(r + 8) * 65536 + px] = __floats2half2_rn(c[2], c[3]);
            } else if (j == 1) {
                *(__half2*)&g_k1h[(size_t)r * 65536 + px]       = __floats2half2_rn(c[0], c[1]);
                *(__half2*)&g_k1h[(size_t)(r + 8) * 65536 + px] = __floats2half2_rn(c[2], c[3]);
            } else {
                *(float2*)&g_v1[(size_t)r * 65536 + px]         = make_float2(c[0], c[1]);
                *(float2*)&g_v1[(size_t)(r + 8) * 65536 + px]   = make_float2(c[2], c[3]);
            }
        }
    }
}

// =====================================================================================
// K2: depthwise 3x3 (SAME) + dilated-window scatter. q/k fp16 in+out, v fp32.
// =====================================================================================
#define SK18(r, c) ((r) * 272 + (c) + ((c) >> 4))

__global__ void k2_dwconv_scatter(const float* __restrict__ qw2, const float* __restrict__ qb2,
                                  const float* __restrict__ kvw2, const float* __restrict__ kvb2)
{
    __shared__ float s[18 * 272];
    int c = blockIdx.y;
    int a = blockIdx.x;
    int h0 = a * 16;
    int t = threadIdx.x;

    const __half* srcH = 0; const float* srcF = 0;
    const float* wsrc; const float* bsrc; int cw;
    float* dstf = 0; __half* dsth = 0; int dstc;
    if (c < 128) {
        srcH = g_q1h + (size_t)c * 65536; dsth = g_qw16; dstc = c;
        wsrc = qw2; bsrc = qb2; cw = c;
    } else {
        int ck = c - 128;
        wsrc = kvw2; bsrc = kvb2; cw = ck;
        if (ck < 128) { srcH = g_k1h + (size_t)ck * 65536; dsth = g_kw16; dstc = ck; }
        else          { srcF = g_v1 + (size_t)(ck - 128) * 65536; dstf = g_vw; dstc = ck - 128; }
    }

    float w9[9];
#pragma unroll
    for (int j = 0; j < 9; j++) w9[j] = wsrc[cw * 9 + j];
    float bias = bsrc[cw];

    for (int i = t; i < 18 * 256; i += 256) {
        int rr = i >> 8, ww = i & 255;
        int h = h0 - 1 + rr;
        float v = 0.f;
        if (h >= 0 && h < 256)
            v = srcH ? __half2float(srcH[h * 256 + ww]) : srcF[h * 256 + ww];
        s[SK18(rr, ww)] = v;
    }
    __syncthreads();

    int g = t >> 4, bcol = t & 15;
    for (int j = 0; j < 16; j++) {
        int hh = j, wx = g;
        int wpix = bcol * 16 + wx;
        float acc = bias;
#pragma unroll
        for (int dy = 0; dy < 3; dy++) {
#pragma unroll
            for (int dx = 0; dx < 3; dx++) {
                int ww = wpix + dx - 1;
                float v = (ww >= 0 && ww < 256) ? s[SK18(hh + dy, ww)] : 0.f;
                acc += w9[dy * 3 + dx] * v;
            }
        }
        int win = hh * 16 + wx;
        size_t idx = ((size_t)win * 128 + dstc) * 256 + a * 16 + bcol;
        if (dsth) dsth[idx] = __float2half(acc);
        else      dstf[idx] = acc;
    }
}

// =====================================================================================
// K3: attention, one block per (head, win), 256 threads, fp16 m16n8k16 MMA.
//   R15: occupancy 4 (launch_bounds 256,4; Q prefetch dropped to fit 64 regs);
//   log2e folded into RN -> softmax exp is a single EX2 (no FMUL).
//   smem u32: Kh2 8x264 | Vh 16x132 | Vl 16x132 | Os 2304f | REDS 128f | RN 16f
//   = 35136 B -> 4 CTAs/SM (32 warps).
// =====================================================================================
__global__ void __launch_bounds__(256, 4) k3_attn_mma(float* __restrict__ attn)
{
    extern __shared__ float sm[];
    unsigned* Kh2 = (unsigned*)sm;              // 2112
    unsigned* Vh  = (unsigned*)sm + 2112;       // 2112
    unsigned* Vl  = (unsigned*)sm + 4224;       // 2112
    float* Os   = sm + 6336;                    // 2304 (4 nq x 32 x 18)
    float* REDS = sm + 8640;                    // 128 (also ssq scratch pre-loop)
    float* RN   = sm + 8768;                    // 16

    int t    = threadIdx.x;
    int lane = t & 31, wid = t >> 5;
    int g    = lane >> 2, tig = lane & 3;
    int head = blockIdx.x;
    int win  = blockIdx.y;

    const __half* qb = g_qw16 + ((size_t)win * 128 + head * 16) * 256;
    const __half* kb = g_kw16 + ((size_t)win * 128 + head * 16) * 256;
    const float*  vb = g_vw   + ((size_t)win * 128 + head * 16) * 256;

    // ---- stage K (fp16 -> d-pair smem) + ssq partials ----
    {
        __half kh[16];
#pragma unroll
        for (int d = 0; d < 16; d++) kh[d] = kb[d * 256 + t];
#pragma unroll
        for (int d = 0; d < 16; d++) {
            float kv = __half2float(kh[d]);
            float ssq = kv * kv;
#pragma unroll
            for (int off = 16; off > 0; off >>= 1) ssq += __shfl_xor_sync(0xFFFFFFFFu, ssq, off);
            if (lane == 0) REDS[d * 8 + wid] = ssq;
        }
#pragma unroll
        for (int dp = 0; dp < 8; dp++) {
            __half2 p = __halves2half2(kh[2 * dp], kh[2 * dp + 1]);
            Kh2[dp * 264 + t] = h2u(p);
        }
    }
    // ---- stage V hi/lo (fp32 -> fp16 pair-of-tokens smem) ----
#pragma unroll
    for (int i = 0; i < 8; i++) {
        int d = 2 * i + (t >> 7);
        int j = t & 127;
        float2 v2 = *(const float2*)&vb[d * 256 + 2 * j];
        __half2 vh = __floats2half2_rn(v2.x, v2.y);
        float rx = v2.x - __low2float(vh);
        float ry = v2.y - __high2float(vh);
        __half2 vl = __floats2half2_rn(rx, ry);
        Vh[d * 132 + j] = h2u(vh);
        Vl[d * 132 + j] = h2u(vl);
    }
    __syncthreads();
    if (t < 16) {
        float s = 0.f;
#pragma unroll
        for (int j = 0; j < 8; j++) s += REDS[t * 8 + j];
        // fold log2e so softmax exp becomes a bare EX2 on the mma logits
        RN[t] = 1.4426950408889634f / fmaxf(sqrtf(s), 1e-12f);
    }
    __syncthreads();

    int mt = wid >> 2, nq = wid & 3;     // warp role, fixed across tiles
    int mrow = mt * 16;

    // k-norm(+log2e) scales for the fp16 A-frag d-columns {2tig, 2tig+1, 2tig+8, 2tig+9}
    float rn0 = RN[2 * tig], rn1 = RN[2 * tig + 1];
    float rn2 = RN[2 * tig + 8], rn3 = RN[2 * tig + 9];

    for (int mq = 0; mq < 8; mq++) {
        int m0 = mq * 32;

        // ---- QK: m16 x n64 per warp, ONE K=16 mma per ntile; Q loaded fp16 ----
        float c[8][4];
        {
            const __half* qrow = qb + m0 + mrow;
            unsigned a[4];
            a[0] = h2u(__floats2half2_rn(__half2float(qrow[(2 * tig) * 256 + g]) * rn0,
                                         __half2float(qrow[(2 * tig + 1) * 256 + g]) * rn1));
            a[1] = h2u(__floats2half2_rn(__half2float(qrow[(2 * tig) * 256 + 8 + g]) * rn0,
                                         __half2float(qrow[(2 * tig + 1) * 256 + 8 + g]) * rn1));
            a[2] = h2u(__floats2half2_rn(__half2float(qrow[(2 * tig + 8) * 256 + g]) * rn2,
                                         __half2float(qrow[(2 * tig + 9) * 256 + g]) * rn3));
            a[3] = h2u(__floats2half2_rn(__half2float(qrow[(2 * tig + 8) * 256 + 8 + g]) * rn2,
                                         __half2float(qrow[(2 * tig + 9) * 256 + 8 + g]) * rn3));
#pragma unroll
            for (int nt = 0; nt < 8; nt++) {
                int n0 = nq * 64 + nt * 8;
                c[nt][0] = 0.f; c[nt][1] = 0.f; c[nt][2] = 0.f; c[nt][3] = 0.f;
                unsigned b[2] = { Kh2[tig * 264 + n0 + g],
                                  Kh2[(tig + 4) * 264 + n0 + g] };
                mma_f16(c[nt], a, b);
            }
        }

        // ---- softmax: exp = EX2(logit*log2e_prescaled). rows rA, rB ----
        int rA = mrow + g, rB = mrow + 8 + g;
        {
            float sA = 0.f, sB = 0.f;
#pragma unroll
            for (int nt = 0; nt < 8; nt++) {
                c[nt][0] = ex2f(c[nt][0]); c[nt][1] = ex2f(c[nt][1]);
                c[nt][2] = ex2f(c[nt][2]); c[nt][3] = ex2f(c[nt][3]);
                sA += c[nt][0] + c[nt][1];
                sB += c[nt][2] + c[nt][3];
            }
            sA += __shfl_xor_sync(0xFFFFFFFFu, sA, 1);
            sA += __shfl_xor_sync(0xFFFFFFFFu, sA, 2);
            sB += __shfl_xor_sync(0xFFFFFFFFu, sB, 1);
            sB += __shfl_xor_sync(0xFFFFFFFFu, sB, 2);
            if (tig == 0) { REDS[rA * 4 + nq] = sA; REDS[rB * 4 + nq] = sB; }
        }
        __syncthreads();
        {
            float rinvA = 1.f / (REDS[rA * 4] + REDS[rA * 4 + 1] + REDS[rA * 4 + 2] + REDS[rA * 4 + 3]);
            float rinvB = 1.f / (REDS[rB * 4] + REDS[rB * 4 + 1] + REDS[rB * 4 + 2] + REDS[rB * 4 + 3]);
            float* oA = attn + ((size_t)((win * 8 + head) * 256 + m0 + rA)) * 256;
            float* oB = attn + ((size_t)((win * 8 + head) * 256 + m0 + rB)) * 256;
#pragma unroll
            for (int nt = 0; nt < 8; nt++) {
                int n0 = nq * 64 + nt * 8 + tig * 2;
                c[nt][0] *= rinvA; c[nt][1] *= rinvA;
                c[nt][2] *= rinvB; c[nt][3] *= rinvB;
                __stcs((float2*)&oA[n0], make_float2(c[nt][0], c[nt][1]));
                __stcs((float2*)&oB[n0], make_float2(c[nt][2], c[nt][3]));
            }
        }

        // ---- AV: P C-frags pack DIRECTLY into fp16 A-frags (no shuffles) ----
        {
            float o0[4] = {0.f, 0.f, 0.f, 0.f};   // d 0..7
            float o1[4] = {0.f, 0.f, 0.f, 0.f};   // d 8..15
#pragma unroll
            for (int u = 0; u < 4; u++) {
                int kp = nq * 32 + u * 8;
                unsigned ah[4];
                ah[0] = h2u(__floats2half2_rn(c[2*u][0],   c[2*u][1]));
                ah[1] = h2u(__floats2half2_rn(c[2*u][2],   c[2*u][3]));
                ah[2] = h2u(__floats2half2_rn(c[2*u+1][0], c[2*u+1][1]));
                ah[3] = h2u(__floats2half2_rn(c[2*u+1][2], c[2*u+1][3]));
                unsigned bh0[2] = { Vh[g * 132 + kp + tig], Vh[g * 132 + kp + tig + 4] };
                mma_f16(o0, ah, bh0);
                unsigned bl0[2] = { Vl[g * 132 + kp + tig], Vl[g * 132 + kp + tig + 4] };
                mma_f16(o0, ah, bl0);
                unsigned bh1[2] = { Vh[(8 + g) * 132 + kp + tig], Vh[(8 + g) * 132 + kp + tig + 4] };
                mma_f16(o1, ah, bh1);
                unsigned bl1[2] = { Vl[(8 + g) * 132 + kp + tig], Vl[(8 + g) * 132 + kp + tig + 4] };
                mma_f16(o1, ah, bl1);
            }
            *(float2*)&Os[nq * 576 + (mrow + g) * 18 + tig * 2]         = make_float2(o0[0], o0[1]);
            *(float2*)&Os[nq * 576 + (mrow + 8 + g) * 18 + tig * 2]     = make_float2(o0[2], o0[3]);
            *(float2*)&Os[nq * 576 + (mrow + g) * 18 + 8 + tig * 2]     = make_float2(o1[0], o1[1]);
            *(float2*)&Os[nq * 576 + (mrow + 8 + g) * 18 + 8 + tig * 2] = make_float2(o1[2], o1[3]);
        }
        __syncthreads();

        // ---- reduce 4 nq partials, write out_win [win][c][m] coalesced ----
        {
            float* outw = g_outw;
#pragma unroll
            for (int i = 0; i < 2; i++) {
                int e = i * 256 + t;
                int m = e & 31, d = e >> 5;
                float s = Os[m * 18 + d] + Os[576 + m * 18 + d]
                        + Os[1152 + m * 18 + d] + Os[1728 + m * 18 + d];
                outw[((size_t)win * 128 + head * 16 + d) * 256 + m0 + m] = s;
            }
        }
    }
}

// =====================================================================================
// K4: window reverse for `out`: out_win [win][c][m] -> NCHW (unchanged)
// =====================================================================================
__global__ void k4_winrev(float* __restrict__ outp)
{
    __shared__ float s[16 * 272];
    int a = blockIdx.x;
    int c = blockIdx.y;
    int t = threadIdx.x;
    int g = t >> 4, bcol = t & 15;

    const float* outw = g_outw;
    for (int j = 0; j < 16; j++) {
        float v = outw[((size_t)(j * 16 + g) * 128 + c) * 256 + a * 16 + bcol];
        int col = bcol * 16 + g;
        s[j * 272 + col + (col >> 4)] = v;
    }
    __syncthreads();
    for (int j = 0; j < 16; j++) {
        int col = t;
        outp[(size_t)c * 65536 + (a * 16 + j) * 256 + t] = s[j * 272 + col + (col >> 4)];
    }
}

// =====================================================================================
extern "C" void kernel_launch(void* const* d_in, const int* in_sizes, int n_in,
                              void* d_out, int out_size)
{
    const float* lms   = (const float*)d_in[0];
    const float* pan   = (const float*)d_in[1];
    const float* gms   = (const float*)d_in[2];
    const float* gpan  = (const float*)d_in[3];
    const float* qw1   = (const float*)d_in[4];
    const float* qb1   = (const float*)d_in[5];
    const float* qw2   = (const float*)d_in[6];
    const float* qb2   = (const float*)d_in[7];
    const float* kvw1  = (const float*)d_in[8];
    const float* kvb1  = (const float*)d_in[9];
    const float* kvw2  = (const float*)d_in[10];
    const float* kvb2  = (const float*)d_in[11];

    float* attn = (float*)d_out;                   // (256, 8, 256, 256)
    float* outp = attn + 134217728;                // (1, 128, 256, 256)

    cudaFuncSetAttribute(k1_ln_conv1, cudaFuncAttributeMaxDynamicSharedMemorySize, 69632);
    cudaFuncSetAttribute(k3_attn_mma, cudaFuncAttributeMaxDynamicSharedMemorySize, 35136);

    k1_ln_conv1<<<512, 256, 69632>>>(lms, pan, gms, gpan, qw1, qb1, kvw1, kvb1);
    k2_dwconv_scatter<<<dim3(16, 384), 256>>>(qw2, qb2, kvw2, kvb2);
    k3_attn_mma<<<dim3(8, 256), 256, 35136>>>(attn);
    k4_winrev<<<dim3(16, 128), 256>>>(outp);
}

// round 17
// speedup vs baseline: 1.0078x; 1.0078x over previous
#include <cuda_runtime.h>
#include <cuda_fp16.h>
#include <math.h>

// ---------------- scratch (device globals; no allocations allowed) ----------------
__device__ __half g_q1h[128u * 65536u];         // 16 MB : conv1 q out (NCHW, fp16)
__device__ __half g_k1h[128u * 65536u];         // 16 MB : conv1 k out (NCHW, fp16)
__device__ float  g_v1[128u * 65536u];          // 32 MB : conv1 v out (NCHW, fp32)
__device__ __half g_qw16[256u * 128u * 256u];   // 16 MB : q  [win][c][m] fp16
__device__ __half g_kw16[256u * 128u * 256u];   // 16 MB : k  [win][c][m] fp16
__device__ float  g_vw[256u * 128u * 256u];     // 32 MB : v  [win][c][m] fp32
__device__ float  g_outw[128u * 65536u];        // 32 MB : out_win [win][c][m]

// =====================================================================================
// helpers
// =====================================================================================
__device__ __forceinline__ unsigned f2tf32(float f) {
    unsigned u;
    asm("cvt.rna.tf32.f32 %0, %1;" : "=r"(u) : "f"(f));
    return u;
}
__device__ __forceinline__ float ex2f(float x) {
    float r;
    asm("ex2.approx.f32 %0, %1;" : "=f"(r) : "f"(x));
    return r;
}
__device__ __forceinline__ void mma_tf32(float c[4], const unsigned a[4], const unsigned b[2]) {
    asm volatile(
        "mma.sync.aligned.m16n8k8.row.col.f32.tf32.tf32.f32 "
        "{%0,%1,%2,%3},{%4,%5,%6,%7},{%8,%9},{%0,%1,%2,%3};"
        : "+f"(c[0]), "+f"(c[1]), "+f"(c[2]), "+f"(c[3])
        : "r"(a[0]), "r"(a[1]), "r"(a[2]), "r"(a[3]), "r"(b[0]), "r"(b[1]));
}
__device__ __forceinline__ void mma_f16(float c[4], const unsigned a[4], const unsigned b[2]) {
    asm volatile(
        "mma.sync.aligned.m16n8k16.row.col.f32.f16.f16.f32 "
        "{%0,%1,%2,%3},{%4,%5,%6,%7},{%8,%9},{%0,%1,%2,%3};"
        : "+f"(c[0]), "+f"(c[1]), "+f"(c[2]), "+f"(c[3])
        : "r"(a[0]), "r"(a[1]), "r"(a[2]), "r"(a[3]), "r"(b[0]), "r"(b[1]));
}
__device__ __forceinline__ unsigned h2u(__half2 h) { return *reinterpret_cast<unsigned*>(&h); }

// =====================================================================================
// K1: LN + 1x1 convs as tf32 tensor GEMM with x hi/lo compensation. (unchanged)
// =====================================================================================
__global__ void __launch_bounds__(256, 2) k1_ln_conv1(
    const float* __restrict__ lms, const float* __restrict__ pan,
    const float* __restrict__ gms, const float* __restrict__ gpan,
    const float* __restrict__ qw1, const float* __restrict__ qb1,
    const float* __restrict__ kvw1, const float* __restrict__ kvb1)
{
    extern __shared__ float sw[];
    unsigned* Xh = (unsigned*)sw;            // 64 x 136
    unsigned* Xl = (unsigned*)(sw + 8704);   // 64 x 136

    int t = threadIdx.x;
    int lane = t & 31, w = t >> 5;
    int g = lane >> 2, tig = lane & 3;
    int p0 = blockIdx.x * 128;

    unsigned a[3][4][4];
    float bias0[3], bias1[3];
#pragma unroll
    for (int j = 0; j < 3; j++) {
        int R = j * 128 + w * 16;
        const float* Wsrc = (j == 0) ? qw1 : kvw1;
        int r0 = (j == 0) ? R : (R - 128);
#pragma unroll
        for (int ks = 0; ks < 4; ks++) {
            int k0 = ks * 8;
            a[j][ks][0] = f2tf32(Wsrc[(r0 + g) * 32 + k0 + tig]);
            a[j][ks][1] = f2tf32(Wsrc[(r0 + 8 + g) * 32 + k0 + tig]);
            a[j][ks][2] = f2tf32(Wsrc[(r0 + g) * 32 + k0 + tig + 4]);
            a[j][ks][3] = f2tf32(Wsrc[(r0 + 8 + g) * 32 + k0 + tig + 4]);
        }
        const float* Bsrc = (j == 0) ? qb1 : kvb1;
        bias0[j] = Bsrc[r0 + g];
        bias1[j] = Bsrc[r0 + 8 + g];
    }

    {
        int which = t >> 7;
        int px = t & 127;
        const float* src = which ? lms : pan;
        const float* gg  = which ? gms : gpan;
        float x[32];
        float s = 0.f, s2 = 0.f;
#pragma unroll
        for (int i = 0; i < 32; i++) {
            float v = src[i * 65536 + p0 + px];
            x[i] = v; s += v; s2 += v * v;
        }
        float m = s * (1.f / 32.f);
        float var = s2 * (1.f / 32.f) - m * m;
        float r = rsqrtf(var + 1e-5f);
#pragma unroll
        for (int i = 0; i < 32; i++) {
            float xn = (x[i] - m) * r * gg[i];
            unsigned xh = f2tf32(xn);
            unsigned xl = f2tf32(xn - __uint_as_float(xh));
            int row = which * 32 + i;
            Xh[row * 136 + px] = xh;
            Xl[row * 136 + px] = xl;
        }
    }
    __syncthreads();

    for (int nt = 0; nt < 16; nt++) {
        int n0 = nt * 8;
#pragma unroll
        for (int j = 0; j < 3; j++) {
            int xrow = (j > 0) ? 32 : 0;
            float c[4] = {bias0[j], bias0[j], bias1[j], bias1[j]};
#pragma unroll
            for (int ks = 0; ks < 4; ks++) {
                int k0 = ks * 8;
                unsigned bh[2] = { Xh[(xrow + k0 + tig) * 136 + n0 + g],
                                   Xh[(xrow + k0 + tig + 4) * 136 + n0 + g] };
                mma_tf32(c, a[j][ks], bh);
                unsigned bl[2] = { Xl[(xrow + k0 + tig) * 136 + n0 + g],
                                   Xl[(xrow + k0 + tig + 4) * 136 + n0 + g] };
                mma_tf32(c, a[j][ks], bl);
            }
            int r = w * 16 + g;
            size_t px = (size_t)(p0 + n0 + tig * 2);
            if (j == 0) {
                *(__half2*)&g_q1h[(size_t)r * 65536 + px]       = __floats2half2_rn(c[0], c[1]);
                *(__half2*)&g_q1h[(size_t)(r + 8) * 65536 + px] = __floats2half2_rn(c[2], c[3]);
            } else if (j == 1) {
                *(__half2*)&g_k1h[(size_t)r * 65536 + px]       = __floats2half2_rn(c[0], c[1]);
                *(__half2*)&g_k1h[(size_t)(r + 8) * 65536 + px] = __floats2half2_rn(c[2], c[3]);
            } else {
                *(float2*)&g_v1[(size_t)r * 65536 + px]         = make_float2(c[0], c[1]);
                *(float2*)&g_v1[(size_t)(r + 8) * 65536 + px]   = make_float2(c[2], c[3]);
            }
        }
    }
}

// =====================================================================================
// K2: depthwise 3x3 (SAME) + dilated-window scatter. q/k fp16 in+out, v fp32.
// =====================================================================================
#define SK18(r, c) ((r) * 272 + (c) + ((c) >> 4))

__global__ void k2_dwconv_scatter(const float* __restrict__ qw2, const float* __restrict__ qb2,
                                  const float* __restrict__ kvw2, const float* __restrict__ kvb2)
{
    __shared__ float s[18 * 272];
    int c = blockIdx.y;
    int a = blockIdx.x;
    int h0 = a * 16;
    int t = threadIdx.x;

    const __half* srcH = 0; const float* srcF = 0;
    const float* wsrc; const float* bsrc; int cw;
    float* dstf = 0; __half* dsth = 0; int dstc;
    if (c < 128) {
        srcH = g_q1h + (size_t)c * 65536; dsth = g_qw16; dstc = c;
        wsrc = qw2; bsrc = qb2; cw = c;
    } else {
        int ck = c - 128;
        wsrc = kvw2; bsrc = kvb2; cw = ck;
        if (ck < 128) { srcH = g_k1h + (size_t)ck * 65536; dsth = g_kw16; dstc = ck; }
        else          { srcF = g_v1 + (size_t)(ck - 128) * 65536; dstf = g_vw; dstc = ck - 128; }
    }

    float w9[9];
#pragma unroll
    for (int j = 0; j < 9; j++) w9[j] = wsrc[cw * 9 + j];
    float bias = bsrc[cw];

    for (int i = t; i < 18 * 256; i += 256) {
        int rr = i >> 8, ww = i & 255;
        int h = h0 - 1 + rr;
        float v = 0.f;
        if (h >= 0 && h < 256)
            v = srcH ? __half2float(srcH[h * 256 + ww]) : srcF[h * 256 + ww];
        s[SK18(rr, ww)] = v;
    }
    __syncthreads();

    int g = t >> 4, bcol = t & 15;
    for (int j = 0; j < 16; j++) {
        int hh = j, wx = g;
        int wpix = bcol * 16 + wx;
        float acc = bias;
#pragma unroll
        for (int dy = 0; dy < 3; dy++) {
#pragma unroll
            for (int dx = 0; dx < 3; dx++) {
                int ww = wpix + dx - 1;
                float v = (ww >= 0 && ww < 256) ? s[SK18(hh + dy, ww)] : 0.f;
                acc += w9[dy * 3 + dx] * v;
            }
        }
        int win = hh * 16 + wx;
        size_t idx = ((size_t)win * 128 + dstc) * 256 + a * 16 + bcol;
        if (dsth) dsth[idx] = __float2half(acc);
        else      dstf[idx] = acc;
    }
}

// =====================================================================================
// K3: attention, one block per (head, win), 256 threads, fp16 m16n8k16 MMA.
//   R16 = R14 config (launch_bounds(256,3), Q prefetch) + EX2 fold (log2e into RN).
//   smem u32: Kh2 8x264 | Vh 16x132 | Vl 16x132 | Os 2304f | REDS 128f | RN 16f
// =====================================================================================
__global__ void __launch_bounds__(256, 3) k3_attn_mma(float* __restrict__ attn)
{
    extern __shared__ float sm[];
    unsigned* Kh2 = (unsigned*)sm;              // 2112
    unsigned* Vh  = (unsigned*)sm + 2112;       // 2112
    unsigned* Vl  = (unsigned*)sm + 4224;       // 2112
    float* Os   = sm + 6336;                    // 2304 (4 nq x 32 x 18)
    float* REDS = sm + 8640;                    // 128 (also ssq scratch pre-loop)
    float* RN   = sm + 8768;                    // 16

    int t    = threadIdx.x;
    int lane = t & 31, wid = t >> 5;
    int g    = lane >> 2, tig = lane & 3;
    int head = blockIdx.x;
    int win  = blockIdx.y;

    const __half* qb = g_qw16 + ((size_t)win * 128 + head * 16) * 256;
    const __half* kb = g_kw16 + ((size_t)win * 128 + head * 16) * 256;
    const float*  vb = g_vw   + ((size_t)win * 128 + head * 16) * 256;

    // ---- stage K (fp16 -> d-pair smem) + ssq partials ----
    {
        __half kh[16];
#pragma unroll
        for (int d = 0; d < 16; d++) kh[d] = kb[d * 256 + t];
#pragma unroll
        for (int d = 0; d < 16; d++) {
            float kv = __half2float(kh[d]);
            float ssq = kv * kv;
#pragma unroll
            for (int off = 16; off > 0; off >>= 1) ssq += __shfl_xor_sync(0xFFFFFFFFu, ssq, off);
            if (lane == 0) REDS[d * 8 + wid] = ssq;
        }
#pragma unroll
        for (int dp = 0; dp < 8; dp++) {
            __half2 p = __halves2half2(kh[2 * dp], kh[2 * dp + 1]);
            Kh2[dp * 264 + t] = h2u(p);
        }
    }
    // ---- stage V hi/lo (fp32 -> fp16 pair-of-tokens smem) ----
#pragma unroll
    for (int i = 0; i < 8; i++) {
        int d = 2 * i + (t >> 7);
        int j = t & 127;
        float2 v2 = *(const float2*)&vb[d * 256 + 2 * j];
        __half2 vh = __floats2half2_rn(v2.x, v2.y);
        float rx = v2.x - __low2float(vh);
        float ry = v2.y - __high2float(vh);
        __half2 vl = __floats2half2_rn(rx, ry);
        Vh[d * 132 + j] = h2u(vh);
        Vl[d * 132 + j] = h2u(vl);
    }
    __syncthreads();
    if (t < 16) {
        float s = 0.f;
#pragma unroll
        for (int j = 0; j < 8; j++) s += REDS[t * 8 + j];
        // fold log2e so softmax exp becomes a bare EX2 on the mma logits
        RN[t] = 1.4426950408889634f / fmaxf(sqrtf(s), 1e-12f);
    }
    __syncthreads();

    int mt = wid >> 2, nq = wid & 3;     // warp role, fixed across tiles
    int mrow = mt * 16;

    // k-norm(+log2e) scales for the fp16 A-frag d-columns {2tig, 2tig+1, 2tig+8, 2tig+9}
    float rn0 = RN[2 * tig], rn1 = RN[2 * tig + 1];
    float rn2 = RN[2 * tig + 8], rn3 = RN[2 * tig + 9];

    // ---- prefetch Q rows for tile 0 (fp16) ----
    float qn[8];
    {
        const __half* qrow = qb + mrow;
        qn[0] = __half2float(qrow[(2 * tig) * 256 + g]);
        qn[1] = __half2float(qrow[(2 * tig + 1) * 256 + g]);
        qn[2] = __half2float(qrow[(2 * tig) * 256 + 8 + g]);
        qn[3] = __half2float(qrow[(2 * tig + 1) * 256 + 8 + g]);
        qn[4] = __half2float(qrow[(2 * tig + 8) * 256 + g]);
        qn[5] = __half2float(qrow[(2 * tig + 9) * 256 + g]);
        qn[6] = __half2float(qrow[(2 * tig + 8) * 256 + 8 + g]);
        qn[7] = __half2float(qrow[(2 * tig + 9) * 256 + 8 + g]);
    }

    for (int mq = 0; mq < 8; mq++) {
        int m0 = mq * 32;

        // ---- QK: m16 x n64 per warp, ONE K=16 mma per ntile ----
        float c[8][4];
        {
            unsigned a[4];
            a[0] = h2u(__floats2half2_rn(qn[0] * rn0, qn[1] * rn1));
            a[1] = h2u(__floats2half2_rn(qn[2] * rn0, qn[3] * rn1));
            a[2] = h2u(__floats2half2_rn(qn[4] * rn2, qn[5] * rn3));
            a[3] = h2u(__floats2half2_rn(qn[6] * rn2, qn[7] * rn3));
#pragma unroll
            for (int nt = 0; nt < 8; nt++) {
                int n0 = nq * 64 + nt * 8;
                c[nt][0] = 0.f; c[nt][1] = 0.f; c[nt][2] = 0.f; c[nt][3] = 0.f;
                unsigned b[2] = { Kh2[tig * 264 + n0 + g],
                                  Kh2[(tig + 4) * 264 + n0 + g] };
                mma_f16(c[nt], a, b);
            }
        }

        // ---- prefetch next tile's Q (overlaps softmax + stores + AV) ----
        if (mq < 7) {
            const __half* qrow = qb + (mq + 1) * 32 + mrow;
            qn[0] = __half2float(qrow[(2 * tig) * 256 + g]);
            qn[1] = __half2float(qrow[(2 * tig + 1) * 256 + g]);
            qn[2] = __half2float(qrow[(2 * tig) * 256 + 8 + g]);
            qn[3] = __half2float(qrow[(2 * tig + 1) * 256 + 8 + g]);
            qn[4] = __half2float(qrow[(2 * tig + 8) * 256 + g]);
            qn[5] = __half2float(qrow[(2 * tig + 9) * 256 + g]);
            qn[6] = __half2float(qrow[(2 * tig + 8) * 256 + 8 + g]);
            qn[7] = __half2float(qrow[(2 * tig + 9) * 256 + 8 + g]);
        }

        // ---- softmax: exp = EX2(logit, log2e pre-folded). rows rA, rB ----
        int rA = mrow + g, rB = mrow + 8 + g;
        {
            float sA = 0.f, sB = 0.f;
#pragma unroll
            for (int nt = 0; nt < 8; nt++) {
                c[nt][0] = ex2f(c[nt][0]); c[nt][1] = ex2f(c[nt][1]);
                c[nt][2] = ex2f(c[nt][2]); c[nt][3] = ex2f(c[nt][3]);
                sA += c[nt][0] + c[nt][1];
                sB += c[nt][2] + c[nt][3];
            }
            sA += __shfl_xor_sync(0xFFFFFFFFu, sA, 1);
            sA += __shfl_xor_sync(0xFFFFFFFFu, sA, 2);
            sB += __shfl_xor_sync(0xFFFFFFFFu, sB, 1);
            sB += __shfl_xor_sync(0xFFFFFFFFu, sB, 2);
            if (tig == 0) { REDS[rA * 4 + nq] = sA; REDS[rB * 4 + nq] = sB; }
        }
        __syncthreads();
        {
            float rinvA = 1.f / (REDS[rA * 4] + REDS[rA * 4 + 1] + REDS[rA * 4 + 2] + REDS[rA * 4 + 3]);
            float rinvB = 1.f / (REDS[rB * 4] + REDS[rB * 4 + 1] + REDS[rB * 4 + 2] + REDS[rB * 4 + 3]);
            float* oA = attn + ((size_t)((win * 8 + head) * 256 + m0 + rA)) * 256;
            float* oB = attn + ((size_t)((win * 8 + head) * 256 + m0 + rB)) * 256;
#pragma unroll
            for (int nt = 0; nt < 8; nt++) {
                int n0 = nq * 64 + nt * 8 + tig * 2;
                c[nt][0] *= rinvA; c[nt][1] *= rinvA;
                c[nt][2] *= rinvB; c[nt][3] *= rinvB;
                __stcs((float2*)&oA[n0], make_float2(c[nt][0], c[nt][1]));
                __stcs((float2*)&oB[n0], make_float2(c[nt][2], c[nt][3]));
            }
        }

        // ---- AV: P C-frags pack DIRECTLY into fp16 A-frags (no shuffles) ----
        {
            float o0[4] = {0.f, 0.f, 0.f, 0.f};   // d 0..7
            float o1[4] = {0.f, 0.f, 0.f, 0.f};   // d 8..15
#pragma unroll
            for (int u = 0; u < 4; u++) {
                int kp = nq * 32 + u * 8;
                unsigned ah[4];
                ah[0] = h2u(__floats2half2_rn(c[2*u][0],   c[2*u][1]));
                ah[1] = h2u(__floats2half2_rn(c[2*u][2],   c[2*u][3]));
                ah[2] = h2u(__floats2half2_rn(c[2*u+1][0], c[2*u+1][1]));
                ah[3] = h2u(__floats2half2_rn(c[2*u+1][2], c[2*u+1][3]));
                unsigned bh0[2] = { Vh[g * 132 + kp + tig], Vh[g * 132 + kp + tig + 4] };
                mma_f16(o0, ah, bh0);
                unsigned bl0[2] = { Vl[g * 132 + kp + tig], Vl[g * 132 + kp + tig + 4] };
                mma_f16(o0, ah, bl0);
                unsigned bh1[2] = { Vh[(8 + g) * 132 + kp + tig], Vh[(8 + g) * 132 + kp + tig + 4] };
                mma_f16(o1, ah, bh1);
                unsigned bl1[2] = { Vl[(8 + g) * 132 + kp + tig], Vl[(8 + g) * 132 + kp + tig + 4] };
                mma_f16(o1, ah, bl1);
            }
            *(float2*)&Os[nq * 576 + (mrow + g) * 18 + tig * 2]         = make_float2(o0[0], o0[1]);
            *(float2*)&Os[nq * 576 + (mrow + 8 + g) * 18 + tig * 2]     = make_float2(o0[2], o0[3]);
            *(float2*)&Os[nq * 576 + (mrow + g) * 18 + 8 + tig * 2]     = make_float2(o1[0], o1[1]);
            *(float2*)&Os[nq * 576 + (mrow + 8 + g) * 18 + 8 + tig * 2] = make_float2(o1[2], o1[3]);
        }
        __syncthreads();

        // ---- reduce 4 nq partials, write out_win [win][c][m] coalesced ----
        {
            float* outw = g_outw;
#pragma unroll
            for (int i = 0; i < 2; i++) {
                int e = i * 256 + t;
                int m = e & 31, d = e >> 5;
                float s = Os[m * 18 + d] + Os[576 + m * 18 + d]
                        + Os[1152 + m * 18 + d] + Os[1728 + m * 18 + d];
                outw[((size_t)win * 128 + head * 16 + d) * 256 + m0 + m] = s;
            }
        }
    }
}

// =====================================================================================
// K4: window reverse for `out`: out_win [win][c][m] -> NCHW (unchanged)
// =====================================================================================
__global__ void k4_winrev(float* __restrict__ outp)
{
    __shared__ float s[16 * 272];
    int a = blockIdx.x;
    int c = blockIdx.y;
    int t = threadIdx.x;
    int g = t >> 4, bcol = t & 15;

    const float* outw = g_outw;
    for (int j = 0; j < 16; j++) {
        float v = outw[((size_t)(j * 16 + g) * 128 + c) * 256 + a * 16 + bcol];
        int col = bcol * 16 + g;
        s[j * 272 + col + (col >> 4)] = v;
    }
    __syncthreads();
    for (int j = 0; j < 16; j++) {
        int col = t;
        outp[(size_t)c * 65536 + (a * 16 + j) * 256 + t] = s[j * 272 + col + (col >> 4)];
    }
}

// =====================================================================================
extern "C" void kernel_launch(void* const* d_in, const int* in_sizes, int n_in,
                              void* d_out, int out_size)
{
    const float* lms   = (const float*)d_in[0];
    const float* pan   = (const float*)d_in[1];
    const float* gms   = (const float*)d_in[2];
    const float* gpan  = (const float*)d_in[3];
    const float* qw1   = (const float*)d_in[4];
    const float* qb1   = (const float*)d_in[5];
    const float* qw2   = (const float*)d_in[6];
    const float* qb2   = (const float*)d_in[7];
    const float* kvw1  = (const float*)d_in[8];
    const float* kvb1  = (const float*)d_in[9];
    const float* kvw2  = (const float*)d_in[10];
    const float* kvb2  = (const float*)d_in[11];

    float* attn = (float*)d_out;                   // (256, 8, 256, 256)
    float* outp = attn + 134217728;                // (1, 128, 256, 256)

    cudaFuncSetAttribute(k1_ln_conv1, cudaFuncAttributeMaxDynamicSharedMemorySize, 69632);
    cudaFuncSetAttribute(k3_attn_mma, cudaFuncAttributeMaxDynamicSharedMemorySize, 35136);

    k1_ln_conv1<<<512, 256, 69632>>>(lms, pan, gms, gpan, qw1, qb1, kvw1, kvb1);
    k2_dwconv_scatter<<<dim3(16, 384), 256>>>(qw2, qb2, kvw2, kvb2);
    k3_attn_mma<<<dim3(8, 256), 256, 35136>>>(attn);
    k4_winrev<<<dim3(16, 128), 256>>>(outp);
}